// round 16
// baseline (speedup 1.0000x reference)
#include <cuda_runtime.h>
#include <cuda_bf16.h>
#include <cstdint>

#define NN 50000
#define NE 1600000

__device__ float g_agg[NN * 16];        // scatter-sum of e_new by dst
// pre-split weights (bf16 hi/lo), written once by prep_kernel
__device__ __nv_bfloat16 g_W1T_hi[64 * 48];   // [n][k] rows 96B
__device__ __nv_bfloat16 g_W1T_lo[64 * 48];
__device__ __nv_bfloat16 g_W2T_hi[16 * 64];   // [n][k] rows 128B
__device__ __nv_bfloat16 g_W2T_lo[16 * 64];

// ---------------- dynamic smem layout (bytes), 256 edges/block ----------------
#define AROWB  112                 // A row stride (k<48 used; 112B: conflict-free)
#define WROWB  112                 // W1T row stride
#define W2ROWB 144                 // W2T row stride
#define S_AHI  0                   // A hi  [256][112]
#define S_ALO  28672               // A lo
#define S_W1HI 57344               // W1T hi [64][112]
#define S_W1LO 64512
#define S_W2HI 71680               // W2T hi [16][144]
#define S_W2LO 73984
#define S_B1F  76288               // b1 (64 f32)
#define S_B2F  76544               // b2 (16 f32)
#define S_DIDX 76608               // dst index (256 i32)
#define SMEM_TOTAL 77632

__device__ __forceinline__ uint32_t pack_split(float v0, float v1, uint32_t& lopack) {
    __nv_bfloat16 h0 = __float2bfloat16(v0);
    __nv_bfloat16 h1 = __float2bfloat16(v1);
    __nv_bfloat16 l0 = __float2bfloat16(v0 - __bfloat162float(h0));
    __nv_bfloat16 l1 = __float2bfloat16(v1 - __bfloat162float(h1));
    lopack = (uint32_t)__bfloat16_as_ushort(l0) | ((uint32_t)__bfloat16_as_ushort(l1) << 16);
    return (uint32_t)__bfloat16_as_ushort(h0) | ((uint32_t)__bfloat16_as_ushort(h1) << 16);
}
__device__ __forceinline__ void ldmx4(uint32_t* r, uint32_t a) {
    asm volatile("ldmatrix.sync.aligned.m8n8.x4.shared.b16 {%0,%1,%2,%3}, [%4];"
        : "=r"(r[0]), "=r"(r[1]), "=r"(r[2]), "=r"(r[3]) : "r"(a));
}
__device__ __forceinline__ void mma_bf16(float* c, const uint32_t* a,
                                         uint32_t b0, uint32_t b1) {
    asm volatile("mma.sync.aligned.m16n8k16.row.col.f32.bf16.bf16.f32 "
        "{%0,%1,%2,%3}, {%4,%5,%6,%7}, {%8,%9}, {%0,%1,%2,%3};"
        : "+f"(c[0]), "+f"(c[1]), "+f"(c[2]), "+f"(c[3])
        : "r"(a[0]), "r"(a[1]), "r"(a[2]), "r"(a[3]), "r"(b0), "r"(b1));
}
__device__ __forceinline__ uint32_t smem_u32(const void* p) {
    uint32_t a;
    asm("{ .reg .u64 t; cvta.to.shared.u64 t, %1; cvt.u32.u64 %0, t; }" : "=r"(a) : "l"(p));
    return a;
}

// ---------------------------------------------------------------------------
__global__ void zero_agg_kernel() {
    int i = blockIdx.x * 256 + threadIdx.x;
    if (i < NN * 16 / 4) ((float4*)g_agg)[i] = make_float4(0.f, 0.f, 0.f, 0.f);
}

// one-time weight split: W1T[n][k] = W1[k][n], hi/lo bf16; same for W2T.
__global__ void prep_kernel(const float* __restrict__ W1, const float* __restrict__ W2) {
    int t = blockIdx.x * 256 + threadIdx.x;
    if (t < 64 * 48) {
        int n = t / 48, k = t % 48;
        float v = W1[k * 64 + n];
        __nv_bfloat16 h = __float2bfloat16(v);
        g_W1T_hi[t] = h;
        g_W1T_lo[t] = __float2bfloat16(v - __bfloat162float(h));
    }
    if (t < 16 * 64) {
        int n = t / 64, k = t % 64;
        float v = W2[k * 16 + n];
        __nv_bfloat16 h = __float2bfloat16(v);
        g_W2T_hi[t] = h;
        g_W2T_lo[t] = __float2bfloat16(v - __bfloat162float(h));
    }
}

// ---------------------------------------------------------------------------
// mma.sync edge kernel v3: 256 edges/block, 8 warps. Chain-spaced term-major
// mma ordering (each accumulator's dependent writes 8 apart in GEMM1, 4 in
// GEMM2). h fragment-chained in registers (no smem round-trip).
// ---------------------------------------------------------------------------
__global__ void __launch_bounds__(256, 2) edge_kernel(
    const float* __restrict__ x,
    const int* __restrict__ ei, const float* __restrict__ e_in,
    const float* __restrict__ b1g, const float* __restrict__ b2g,
    float* __restrict__ e_out, int block_off)
{
    extern __shared__ char dsm[];
    const uint32_t sb = smem_u32(dsm);
    const int tid = threadIdx.x;
    const int l = tid & 31;
    const int w = tid >> 5;
    const int base = (blockIdx.x + block_off) * 256;

    // ---- gather m_in row (edge = base+tid), split, stage (k<48 only) ----
    const int si = ei[base + tid];
    const int di = ei[NE + base + tid];
    ((int*)(dsm + S_DIDX))[tid] = di;
    {
        float mv[48];
#pragma unroll
        for (int q = 0; q < 4; q++) {
            float4 v = *((const float4*)(x + di * 16) + q);
            mv[q*4+0]=v.x; mv[q*4+1]=v.y; mv[q*4+2]=v.z; mv[q*4+3]=v.w;
        }
#pragma unroll
        for (int q = 0; q < 4; q++) {
            float4 v = *((const float4*)(x + si * 16) + q);
            mv[16+q*4+0]=v.x; mv[16+q*4+1]=v.y; mv[16+q*4+2]=v.z; mv[16+q*4+3]=v.w;
        }
#pragma unroll
        for (int q = 0; q < 4; q++) {
            float4 v = *((const float4*)(e_in + (base + tid) * 16) + q);
            mv[32+q*4+0]=v.x; mv[32+q*4+1]=v.y; mv[32+q*4+2]=v.z; mv[32+q*4+3]=v.w;
        }
        uint32_t hi[24], lo[24];
#pragma unroll
        for (int c = 0; c < 24; c++) hi[c] = pack_split(mv[2*c], mv[2*c+1], lo[c]);
        char* rh = dsm + S_AHI + tid * AROWB;
        char* rl = dsm + S_ALO + tid * AROWB;
#pragma unroll
        for (int i = 0; i < 6; i++) {
            *(uint4*)(rh + i*16) = make_uint4(hi[4*i], hi[4*i+1], hi[4*i+2], hi[4*i+3]);
            *(uint4*)(rl + i*16) = make_uint4(lo[4*i], lo[4*i+1], lo[4*i+2], lo[4*i+3]);
        }
    }

    // ---- stage pre-split weights (plain uint4 copies) ----
    for (int t = tid; t < 384; t += 256) {            // W1T: 64 rows x 96B
        int n = t / 6, off = (t % 6) * 16;
        *(uint4*)(dsm + S_W1HI + n * WROWB + off) = *(const uint4*)((const char*)g_W1T_hi + n * 96 + off);
        *(uint4*)(dsm + S_W1LO + n * WROWB + off) = *(const uint4*)((const char*)g_W1T_lo + n * 96 + off);
    }
    for (int t = tid; t < 128; t += 256) {            // W2T: 16 rows x 128B
        int n = t / 8, off = (t % 8) * 16;
        *(uint4*)(dsm + S_W2HI + n * W2ROWB + off) = *(const uint4*)((const char*)g_W2T_hi + n * 128 + off);
        *(uint4*)(dsm + S_W2LO + n * W2ROWB + off) = *(const uint4*)((const char*)g_W2T_lo + n * 128 + off);
    }
    if (tid < 64) ((float*)(dsm + S_B1F))[tid] = b1g[tid];
    if (tid < 16) ((float*)(dsm + S_B2F))[tid] = b2g[tid];
    __syncthreads();

    // ---- GEMM1: c1[2m][8n], kk = 0..2, np-pair blocks, term-major ----
    float c1[2][8][4];
#pragma unroll
    for (int mt = 0; mt < 2; mt++)
#pragma unroll
        for (int nt = 0; nt < 8; nt++)
#pragma unroll
            for (int i = 0; i < 4; i++) c1[mt][nt][i] = 0.f;

    const uint32_t aAddr = sb + S_AHI + (w * 32 + (l & 15)) * AROWB + (l >> 4) * 16;
    const uint32_t bAddr = sb + S_W1HI + (l & 15) * WROWB + (l >> 4) * 16;
#pragma unroll
    for (int kk = 0; kk < 3; kk++) {
        uint32_t a_hi[2][4], a_lo[2][4];
#pragma unroll
        for (int mt = 0; mt < 2; mt++) {
            uint32_t ad = aAddr + mt * 16 * AROWB + kk * 32;
            ldmx4(a_hi[mt], ad);
            ldmx4(a_lo[mt], ad + (S_ALO - S_AHI));
        }
#pragma unroll
        for (int pp = 0; pp < 2; pp++) {             // np = 2pp, 2pp+1
            uint32_t r0[4], s0[4], r1[4], s1[4];
            uint32_t bd0 = bAddr + (2*pp)     * 16 * WROWB + kk * 32;
            uint32_t bd1 = bAddr + (2*pp + 1) * 16 * WROWB + kk * 32;
            ldmx4(r0, bd0);
            ldmx4(s0, bd0 + (S_W1LO - S_W1HI));
            ldmx4(r1, bd1);
            ldmx4(s1, bd1 + (S_W1LO - S_W1HI));
            float* a0 = c1[0][4*pp+0]; float* a1 = c1[0][4*pp+1];
            float* a2 = c1[0][4*pp+2]; float* a3 = c1[0][4*pp+3];
            float* b0 = c1[1][4*pp+0]; float* b1 = c1[1][4*pp+1];
            float* b2 = c1[1][4*pp+2]; float* b3 = c1[1][4*pp+3];
            // term 0: hi @ hi — 8 independent mmas
            mma_bf16(a0, a_hi[0], r0[0], r0[2]);
            mma_bf16(a1, a_hi[0], r0[1], r0[3]);
            mma_bf16(a2, a_hi[0], r1[0], r1[2]);
            mma_bf16(a3, a_hi[0], r1[1], r1[3]);
            mma_bf16(b0, a_hi[1], r0[0], r0[2]);
            mma_bf16(b1, a_hi[1], r0[1], r0[3]);
            mma_bf16(b2, a_hi[1], r1[0], r1[2]);
            mma_bf16(b3, a_hi[1], r1[1], r1[3]);
            // term 1: hi @ lo
            mma_bf16(a0, a_hi[0], s0[0], s0[2]);
            mma_bf16(a1, a_hi[0], s0[1], s0[3]);
            mma_bf16(a2, a_hi[0], s1[0], s1[2]);
            mma_bf16(a3, a_hi[0], s1[1], s1[3]);
            mma_bf16(b0, a_hi[1], s0[0], s0[2]);
            mma_bf16(b1, a_hi[1], s0[1], s0[3]);
            mma_bf16(b2, a_hi[1], s1[0], s1[2]);
            mma_bf16(b3, a_hi[1], s1[1], s1[3]);
            // term 2: lo @ hi
            mma_bf16(a0, a_lo[0], r0[0], r0[2]);
            mma_bf16(a1, a_lo[0], r0[1], r0[3]);
            mma_bf16(a2, a_lo[0], r1[0], r1[2]);
            mma_bf16(a3, a_lo[0], r1[1], r1[3]);
            mma_bf16(b0, a_lo[1], r0[0], r0[2]);
            mma_bf16(b1, a_lo[1], r0[1], r0[3]);
            mma_bf16(b2, a_lo[1], r1[0], r1[2]);
            mma_bf16(b3, a_lo[1], r1[1], r1[3]);
        }
    }

    // ---- h = relu(c1 + b1) IN REGISTERS ----
#pragma unroll
    for (int nt = 0; nt < 8; nt++) {
        float2 bp = *(float2*)(dsm + S_B1F + (nt * 8 + (l & 3) * 2) * 4);
#pragma unroll
        for (int mt = 0; mt < 2; mt++) {
            c1[mt][nt][0] = fmaxf(c1[mt][nt][0] + bp.x, 0.f);
            c1[mt][nt][1] = fmaxf(c1[mt][nt][1] + bp.y, 0.f);
            c1[mt][nt][2] = fmaxf(c1[mt][nt][2] + bp.x, 0.f);
            c1[mt][nt][3] = fmaxf(c1[mt][nt][3] + bp.y, 0.f);
        }
    }

    // ---- GEMM2: A chained from c1; term-major, 4 independent accs ----
    float c2[2][2][4];
#pragma unroll
    for (int mt = 0; mt < 2; mt++)
#pragma unroll
        for (int nt = 0; nt < 2; nt++)
#pragma unroll
            for (int i = 0; i < 4; i++) c2[mt][nt][i] = 0.f;

    const uint32_t b2Addr = sb + S_W2HI + (l & 15) * W2ROWB + (l >> 4) * 16;
#pragma unroll
    for (int kk = 0; kk < 4; kk++) {
        uint32_t r[4], s[4];
        ldmx4(r, b2Addr + kk * 32);
        ldmx4(s, b2Addr + kk * 32 + (S_W2LO - S_W2HI));
        uint32_t a_hi[2][4], a_lo[2][4];
#pragma unroll
        for (int mt = 0; mt < 2; mt++) {
            a_hi[mt][0] = pack_split(c1[mt][2*kk][0],   c1[mt][2*kk][1],   a_lo[mt][0]);
            a_hi[mt][1] = pack_split(c1[mt][2*kk][2],   c1[mt][2*kk][3],   a_lo[mt][1]);
            a_hi[mt][2] = pack_split(c1[mt][2*kk+1][0], c1[mt][2*kk+1][1], a_lo[mt][2]);
            a_hi[mt][3] = pack_split(c1[mt][2*kk+1][2], c1[mt][2*kk+1][3], a_lo[mt][3]);
        }
        // term 0: hi @ hi — 4 independent
        mma_bf16(c2[0][0], a_hi[0], r[0], r[2]);
        mma_bf16(c2[0][1], a_hi[0], r[1], r[3]);
        mma_bf16(c2[1][0], a_hi[1], r[0], r[2]);
        mma_bf16(c2[1][1], a_hi[1], r[1], r[3]);
        // term 1: hi @ lo
        mma_bf16(c2[0][0], a_hi[0], s[0], s[2]);
        mma_bf16(c2[0][1], a_hi[0], s[1], s[3]);
        mma_bf16(c2[1][0], a_hi[1], s[0], s[2]);
        mma_bf16(c2[1][1], a_hi[1], s[1], s[3]);
        // term 2: lo @ hi
        mma_bf16(c2[0][0], a_lo[0], r[0], r[2]);
        mma_bf16(c2[0][1], a_lo[0], r[1], r[3]);
        mma_bf16(c2[1][0], a_lo[1], r[0], r[2]);
        mma_bf16(c2[1][1], a_lo[1], r[1], r[3]);
    }

    // ---- epilogue: +b2, store e_new (float2), scatter atomics ----
    float2 b2p[2];
#pragma unroll
    for (int nt = 0; nt < 2; nt++)
        b2p[nt] = *(float2*)(dsm + S_B2F + (nt * 8 + (l & 3) * 2) * 4);
#pragma unroll
    for (int mt = 0; mt < 2; mt++) {
        int r0 = w * 32 + mt * 16 + (l >> 2);
        int d0 = ((int*)(dsm + S_DIDX))[r0];
        int d1 = ((int*)(dsm + S_DIDX))[r0 + 8];
#pragma unroll
        for (int nt = 0; nt < 2; nt++) {
            int jc = nt * 8 + (l & 3) * 2;
            float v0 = c2[mt][nt][0] + b2p[nt].x;
            float v1 = c2[mt][nt][1] + b2p[nt].y;
            *(float2*)&e_out[(base + r0) * 16 + jc] = make_float2(v0, v1);
            atomicAdd(g_agg + d0 * 16 + jc,     v0);
            atomicAdd(g_agg + d0 * 16 + jc + 1, v1);
            v0 = c2[mt][nt][2] + b2p[nt].x;
            v1 = c2[mt][nt][3] + b2p[nt].y;
            *(float2*)&e_out[(base + r0 + 8) * 16 + jc] = make_float2(v0, v1);
            atomicAdd(g_agg + d1 * 16 + jc,     v0);
            atomicAdd(g_agg + d1 * 16 + jc + 1, v1);
        }
    }
}

// ---------------------------------------------------------------------------
// node MLP split-j: 2 threads per node (j halves), combined via shfl.
// ---------------------------------------------------------------------------
__global__ void __launch_bounds__(256) node_kernel(
    const float* __restrict__ x,
    const float* __restrict__ W1, const float* __restrict__ b1,
    const float* __restrict__ W2, const float* __restrict__ b2,
    float* __restrict__ x_out)
{
    __shared__ float sW1[32 * 64];
    __shared__ float sW2[64 * 16];
    __shared__ float sb1[64];
    __shared__ float sb2[16];
    int tid = threadIdx.x;
#pragma unroll
    for (int r = 0; r < 8; r++) sW1[r * 256 + tid] = W1[r * 256 + tid];
#pragma unroll
    for (int r = 0; r < 4; r++) sW2[r * 256 + tid] = W2[r * 256 + tid];
    if (tid < 64) sb1[tid] = b1[tid];
    if (tid < 16) sb2[tid] = b2[tid];
    __syncthreads();

    int gt = blockIdx.x * 256 + tid;
    int n = gt >> 1;
    int half = gt & 1;
    if (n >= NN) return;

    float in[32];
#pragma unroll
    for (int q = 0; q < 4; q++) {
        float4 v = ((const float4*)x)[n * 4 + q];
        in[q*4+0]=v.x; in[q*4+1]=v.y; in[q*4+2]=v.z; in[q*4+3]=v.w;
        float4 a = ((const float4*)g_agg)[n * 4 + q];
        in[16+q*4+0]=a.x; in[16+q*4+1]=a.y; in[16+q*4+2]=a.z; in[16+q*4+3]=a.w;
    }
    float o[16];
#pragma unroll
    for (int c = 0; c < 16; c++) o[c] = half ? 0.f : sb2[c];
    int j0 = half * 32;
    for (int j = j0; j < j0 + 32; j++) {
        float h = sb1[j];
#pragma unroll
        for (int k = 0; k < 32; k++) h = fmaf(in[k], sW1[k * 64 + j], h);
        h = fmaxf(h, 0.f);
#pragma unroll
        for (int c = 0; c < 16; c++) o[c] = fmaf(h, sW2[j * 16 + c], o[c]);
    }
    // combine halves (partner = lane xor 1)
#pragma unroll
    for (int c = 0; c < 16; c++)
        o[c] += __shfl_xor_sync(0xffffffffu, o[c], 1);
    if (half == 0) {
#pragma unroll
        for (int q = 0; q < 4; q++)
            ((float4*)x_out)[n * 4 + q] =
                make_float4(o[q*4+0], o[q*4+1], o[q*4+2], o[q*4+3]);
    }
}

// ---------------------------------------------------------------------------
extern "C" void kernel_launch(void* const* d_in, const int* in_sizes, int n_in,
                              void* d_out, int out_size)
{
    const float* x     = (const float*)d_in[0];
    const int*   ei    = (const int*)d_in[1];    // edge_index: int32 (JAX x64 disabled)
    const float* e     = (const float*)d_in[2];
    const float* fRW1  = (const float*)d_in[3];
    const float* fRb1  = (const float*)d_in[4];
    const float* fRW2  = (const float*)d_in[5];
    const float* fRb2  = (const float*)d_in[6];
    const float* fOW1  = (const float*)d_in[7];
    const float* fOb1  = (const float*)d_in[8];
    const float* fOW2  = (const float*)d_in[9];
    const float* fOb2  = (const float*)d_in[10];

    float* x_new = (float*)d_out;            // [NN, 16]
    float* e_new = x_new + NN * 16;          // [NE, 16]

    cudaFuncSetAttribute(edge_kernel, cudaFuncAttributeMaxDynamicSharedMemorySize,
                         SMEM_TOTAL);

    const int EB = NE / 256;                 // 6250 edge blocks
    const int Q  = 1563;                     // 4-way split (R8-proven ncu slot)
    const int QL = EB - 3 * Q;               // 1561

    prep_kernel<<<13, 256>>>(fRW1, fRW2);
    zero_agg_kernel<<<(NN * 16 / 4 + 255) / 256, 256>>>();
    edge_kernel<<<Q,  256, SMEM_TOTAL>>>(x, ei, e, fRb1, fRb2, e_new, 0 * Q);
    edge_kernel<<<Q,  256, SMEM_TOTAL>>>(x, ei, e, fRb1, fRb2, e_new, 1 * Q);
    edge_kernel<<<Q,  256, SMEM_TOTAL>>>(x, ei, e, fRb1, fRb2, e_new, 2 * Q);
    edge_kernel<<<QL, 256, SMEM_TOTAL>>>(x, ei, e, fRb1, fRb2, e_new, 3 * Q);
    node_kernel<<<(2 * NN + 255) / 256, 256>>>(x, fOW1, fOb1, fOW2, fOb2, x_new);
}

// round 17
// speedup vs baseline: 1.1751x; 1.1751x over previous
#include <cuda_runtime.h>
#include <cuda_bf16.h>
#include <cstdint>

#define NN 50000
#define NE 1600000

__device__ float g_agg[NN * 16];        // scatter-sum of e_new by dst
// pre-split weights (bf16 hi/lo), written once by prep_kernel
__device__ __nv_bfloat16 g_W1T_hi[64 * 48];   // [n][k] rows 96B
__device__ __nv_bfloat16 g_W1T_lo[64 * 48];
__device__ __nv_bfloat16 g_W2T_hi[16 * 64];   // [n][k] rows 128B
__device__ __nv_bfloat16 g_W2T_lo[16 * 64];

// ---------------- dynamic smem layout (bytes), 256 edges/block ----------------
#define AROWB  112                 // A row stride (k<48 used; 112B: conflict-free)
#define WROWB  112                 // W1T row stride
#define W2ROWB 144                 // W2T row stride
#define S_AHI  0                   // A hi  [256][112]
#define S_ALO  28672               // A lo
#define S_W1HI 57344               // W1T hi [64][112]
#define S_W1LO 64512
#define S_W2HI 71680               // W2T hi [16][144]
#define S_W2LO 73984
#define S_B1F  76288               // b1 (64 f32)
#define S_B2F  76544               // b2 (16 f32)
#define S_DIDX 76608               // dst index (256 i32)
#define SMEM_TOTAL 77632

__device__ __forceinline__ uint32_t pack_split(float v0, float v1, uint32_t& lopack) {
    __nv_bfloat16 h0 = __float2bfloat16(v0);
    __nv_bfloat16 h1 = __float2bfloat16(v1);
    __nv_bfloat16 l0 = __float2bfloat16(v0 - __bfloat162float(h0));
    __nv_bfloat16 l1 = __float2bfloat16(v1 - __bfloat162float(h1));
    lopack = (uint32_t)__bfloat16_as_ushort(l0) | ((uint32_t)__bfloat16_as_ushort(l1) << 16);
    return (uint32_t)__bfloat16_as_ushort(h0) | ((uint32_t)__bfloat16_as_ushort(h1) << 16);
}
__device__ __forceinline__ void ldmx4(uint32_t* r, uint32_t a) {
    asm volatile("ldmatrix.sync.aligned.m8n8.x4.shared.b16 {%0,%1,%2,%3}, [%4];"
        : "=r"(r[0]), "=r"(r[1]), "=r"(r[2]), "=r"(r[3]) : "r"(a));
}
__device__ __forceinline__ void mma_bf16(float* c, const uint32_t* a,
                                         uint32_t b0, uint32_t b1) {
    asm volatile("mma.sync.aligned.m16n8k16.row.col.f32.bf16.bf16.f32 "
        "{%0,%1,%2,%3}, {%4,%5,%6,%7}, {%8,%9}, {%0,%1,%2,%3};"
        : "+f"(c[0]), "+f"(c[1]), "+f"(c[2]), "+f"(c[3])
        : "r"(a[0]), "r"(a[1]), "r"(a[2]), "r"(a[3]), "r"(b0), "r"(b1));
}
__device__ __forceinline__ uint32_t smem_u32(const void* p) {
    uint32_t a;
    asm("{ .reg .u64 t; cvta.to.shared.u64 t, %1; cvt.u32.u64 %0, t; }" : "=r"(a) : "l"(p));
    return a;
}

// ---------------------------------------------------------------------------
__global__ void zero_agg_kernel() {
    int i = blockIdx.x * 256 + threadIdx.x;
    if (i < NN * 16 / 4) ((float4*)g_agg)[i] = make_float4(0.f, 0.f, 0.f, 0.f);
}

// one-time weight split: W1T[n][k] = W1[k][n], hi/lo bf16; same for W2T.
__global__ void prep_kernel(const float* __restrict__ W1, const float* __restrict__ W2) {
    int t = blockIdx.x * 256 + threadIdx.x;
    if (t < 64 * 48) {
        int n = t / 48, k = t % 48;
        float v = W1[k * 64 + n];
        __nv_bfloat16 h = __float2bfloat16(v);
        g_W1T_hi[t] = h;
        g_W1T_lo[t] = __float2bfloat16(v - __bfloat162float(h));
    }
    if (t < 16 * 64) {
        int n = t / 64, k = t % 64;
        float v = W2[k * 16 + n];
        __nv_bfloat16 h = __float2bfloat16(v);
        g_W2T_hi[t] = h;
        g_W2T_lo[t] = __float2bfloat16(v - __bfloat162float(h));
    }
}

// ---------------------------------------------------------------------------
// mma.sync edge kernel v3: 256 edges/block, 8 warps. Chain-spaced term-major
// mma ordering. h fragment-chained in registers. Single full-grid launch.
// ---------------------------------------------------------------------------
__global__ void __launch_bounds__(256, 2) edge_kernel(
    const float* __restrict__ x,
    const int* __restrict__ ei, const float* __restrict__ e_in,
    const float* __restrict__ b1g, const float* __restrict__ b2g,
    float* __restrict__ e_out)
{
    extern __shared__ char dsm[];
    const uint32_t sb = smem_u32(dsm);
    const int tid = threadIdx.x;
    const int l = tid & 31;
    const int w = tid >> 5;
    const int base = blockIdx.x * 256;

    // ---- gather m_in row (edge = base+tid), split, stage (k<48 only) ----
    const int si = ei[base + tid];
    const int di = ei[NE + base + tid];
    ((int*)(dsm + S_DIDX))[tid] = di;
    {
        float mv[48];
#pragma unroll
        for (int q = 0; q < 4; q++) {
            float4 v = *((const float4*)(x + di * 16) + q);
            mv[q*4+0]=v.x; mv[q*4+1]=v.y; mv[q*4+2]=v.z; mv[q*4+3]=v.w;
        }
#pragma unroll
        for (int q = 0; q < 4; q++) {
            float4 v = *((const float4*)(x + si * 16) + q);
            mv[16+q*4+0]=v.x; mv[16+q*4+1]=v.y; mv[16+q*4+2]=v.z; mv[16+q*4+3]=v.w;
        }
#pragma unroll
        for (int q = 0; q < 4; q++) {
            float4 v = *((const float4*)(e_in + (base + tid) * 16) + q);
            mv[32+q*4+0]=v.x; mv[32+q*4+1]=v.y; mv[32+q*4+2]=v.z; mv[32+q*4+3]=v.w;
        }
        uint32_t hi[24], lo[24];
#pragma unroll
        for (int c = 0; c < 24; c++) hi[c] = pack_split(mv[2*c], mv[2*c+1], lo[c]);
        char* rh = dsm + S_AHI + tid * AROWB;
        char* rl = dsm + S_ALO + tid * AROWB;
#pragma unroll
        for (int i = 0; i < 6; i++) {
            *(uint4*)(rh + i*16) = make_uint4(hi[4*i], hi[4*i+1], hi[4*i+2], hi[4*i+3]);
            *(uint4*)(rl + i*16) = make_uint4(lo[4*i], lo[4*i+1], lo[4*i+2], lo[4*i+3]);
        }
    }

    // ---- stage pre-split weights (plain uint4 copies) ----
    for (int t = tid; t < 384; t += 256) {            // W1T: 64 rows x 96B
        int n = t / 6, off = (t % 6) * 16;
        *(uint4*)(dsm + S_W1HI + n * WROWB + off) = *(const uint4*)((const char*)g_W1T_hi + n * 96 + off);
        *(uint4*)(dsm + S_W1LO + n * WROWB + off) = *(const uint4*)((const char*)g_W1T_lo + n * 96 + off);
    }
    for (int t = tid; t < 128; t += 256) {            // W2T: 16 rows x 128B
        int n = t / 8, off = (t % 8) * 16;
        *(uint4*)(dsm + S_W2HI + n * W2ROWB + off) = *(const uint4*)((const char*)g_W2T_hi + n * 128 + off);
        *(uint4*)(dsm + S_W2LO + n * W2ROWB + off) = *(const uint4*)((const char*)g_W2T_lo + n * 128 + off);
    }
    if (tid < 64) ((float*)(dsm + S_B1F))[tid] = b1g[tid];
    if (tid < 16) ((float*)(dsm + S_B2F))[tid] = b2g[tid];
    __syncthreads();

    // ---- GEMM1: c1[2m][8n], kk = 0..2, np-pair blocks, term-major ----
    float c1[2][8][4];
#pragma unroll
    for (int mt = 0; mt < 2; mt++)
#pragma unroll
        for (int nt = 0; nt < 8; nt++)
#pragma unroll
            for (int i = 0; i < 4; i++) c1[mt][nt][i] = 0.f;

    const uint32_t aAddr = sb + S_AHI + (w * 32 + (l & 15)) * AROWB + (l >> 4) * 16;
    const uint32_t bAddr = sb + S_W1HI + (l & 15) * WROWB + (l >> 4) * 16;
#pragma unroll
    for (int kk = 0; kk < 3; kk++) {
        uint32_t a_hi[2][4], a_lo[2][4];
#pragma unroll
        for (int mt = 0; mt < 2; mt++) {
            uint32_t ad = aAddr + mt * 16 * AROWB + kk * 32;
            ldmx4(a_hi[mt], ad);
            ldmx4(a_lo[mt], ad + (S_ALO - S_AHI));
        }
#pragma unroll
        for (int pp = 0; pp < 2; pp++) {             // np = 2pp, 2pp+1
            uint32_t r0[4], s0[4], r1[4], s1[4];
            uint32_t bd0 = bAddr + (2*pp)     * 16 * WROWB + kk * 32;
            uint32_t bd1 = bAddr + (2*pp + 1) * 16 * WROWB + kk * 32;
            ldmx4(r0, bd0);
            ldmx4(s0, bd0 + (S_W1LO - S_W1HI));
            ldmx4(r1, bd1);
            ldmx4(s1, bd1 + (S_W1LO - S_W1HI));
            float* a0 = c1[0][4*pp+0]; float* a1 = c1[0][4*pp+1];
            float* a2 = c1[0][4*pp+2]; float* a3 = c1[0][4*pp+3];
            float* b0 = c1[1][4*pp+0]; float* b1 = c1[1][4*pp+1];
            float* b2 = c1[1][4*pp+2]; float* b3 = c1[1][4*pp+3];
            // term 0: hi @ hi — 8 independent mmas
            mma_bf16(a0, a_hi[0], r0[0], r0[2]);
            mma_bf16(a1, a_hi[0], r0[1], r0[3]);
            mma_bf16(a2, a_hi[0], r1[0], r1[2]);
            mma_bf16(a3, a_hi[0], r1[1], r1[3]);
            mma_bf16(b0, a_hi[1], r0[0], r0[2]);
            mma_bf16(b1, a_hi[1], r0[1], r0[3]);
            mma_bf16(b2, a_hi[1], r1[0], r1[2]);
            mma_bf16(b3, a_hi[1], r1[1], r1[3]);
            // term 1: hi @ lo
            mma_bf16(a0, a_hi[0], s0[0], s0[2]);
            mma_bf16(a1, a_hi[0], s0[1], s0[3]);
            mma_bf16(a2, a_hi[0], s1[0], s1[2]);
            mma_bf16(a3, a_hi[0], s1[1], s1[3]);
            mma_bf16(b0, a_hi[1], s0[0], s0[2]);
            mma_bf16(b1, a_hi[1], s0[1], s0[3]);
            mma_bf16(b2, a_hi[1], s1[0], s1[2]);
            mma_bf16(b3, a_hi[1], s1[1], s1[3]);
            // term 2: lo @ hi
            mma_bf16(a0, a_lo[0], r0[0], r0[2]);
            mma_bf16(a1, a_lo[0], r0[1], r0[3]);
            mma_bf16(a2, a_lo[0], r1[0], r1[2]);
            mma_bf16(a3, a_lo[0], r1[1], r1[3]);
            mma_bf16(b0, a_lo[1], r0[0], r0[2]);
            mma_bf16(b1, a_lo[1], r0[1], r0[3]);
            mma_bf16(b2, a_lo[1], r1[0], r1[2]);
            mma_bf16(b3, a_lo[1], r1[1], r1[3]);
        }
    }

    // ---- h = relu(c1 + b1) IN REGISTERS ----
#pragma unroll
    for (int nt = 0; nt < 8; nt++) {
        float2 bp = *(float2*)(dsm + S_B1F + (nt * 8 + (l & 3) * 2) * 4);
#pragma unroll
        for (int mt = 0; mt < 2; mt++) {
            c1[mt][nt][0] = fmaxf(c1[mt][nt][0] + bp.x, 0.f);
            c1[mt][nt][1] = fmaxf(c1[mt][nt][1] + bp.y, 0.f);
            c1[mt][nt][2] = fmaxf(c1[mt][nt][2] + bp.x, 0.f);
            c1[mt][nt][3] = fmaxf(c1[mt][nt][3] + bp.y, 0.f);
        }
    }

    // ---- GEMM2: A chained from c1; term-major, 4 independent accs ----
    float c2[2][2][4];
#pragma unroll
    for (int mt = 0; mt < 2; mt++)
#pragma unroll
        for (int nt = 0; nt < 2; nt++)
#pragma unroll
            for (int i = 0; i < 4; i++) c2[mt][nt][i] = 0.f;

    const uint32_t b2Addr = sb + S_W2HI + (l & 15) * W2ROWB + (l >> 4) * 16;
#pragma unroll
    for (int kk = 0; kk < 4; kk++) {
        uint32_t r[4], s[4];
        ldmx4(r, b2Addr + kk * 32);
        ldmx4(s, b2Addr + kk * 32 + (S_W2LO - S_W2HI));
        uint32_t a_hi[2][4], a_lo[2][4];
#pragma unroll
        for (int mt = 0; mt < 2; mt++) {
            a_hi[mt][0] = pack_split(c1[mt][2*kk][0],   c1[mt][2*kk][1],   a_lo[mt][0]);
            a_hi[mt][1] = pack_split(c1[mt][2*kk][2],   c1[mt][2*kk][3],   a_lo[mt][1]);
            a_hi[mt][2] = pack_split(c1[mt][2*kk+1][0], c1[mt][2*kk+1][1], a_lo[mt][2]);
            a_hi[mt][3] = pack_split(c1[mt][2*kk+1][2], c1[mt][2*kk+1][3], a_lo[mt][3]);
        }
        // term 0: hi @ hi — 4 independent
        mma_bf16(c2[0][0], a_hi[0], r[0], r[2]);
        mma_bf16(c2[0][1], a_hi[0], r[1], r[3]);
        mma_bf16(c2[1][0], a_hi[1], r[0], r[2]);
        mma_bf16(c2[1][1], a_hi[1], r[1], r[3]);
        // term 1: hi @ lo
        mma_bf16(c2[0][0], a_hi[0], s[0], s[2]);
        mma_bf16(c2[0][1], a_hi[0], s[1], s[3]);
        mma_bf16(c2[1][0], a_hi[1], s[0], s[2]);
        mma_bf16(c2[1][1], a_hi[1], s[1], s[3]);
        // term 2: lo @ hi
        mma_bf16(c2[0][0], a_lo[0], r[0], r[2]);
        mma_bf16(c2[0][1], a_lo[0], r[1], r[3]);
        mma_bf16(c2[1][0], a_lo[1], r[0], r[2]);
        mma_bf16(c2[1][1], a_lo[1], r[1], r[3]);
    }

    // ---- epilogue: +b2, store e_new (float2), scatter atomics ----
    float2 b2p[2];
#pragma unroll
    for (int nt = 0; nt < 2; nt++)
        b2p[nt] = *(float2*)(dsm + S_B2F + (nt * 8 + (l & 3) * 2) * 4);
#pragma unroll
    for (int mt = 0; mt < 2; mt++) {
        int r0 = w * 32 + mt * 16 + (l >> 2);
        int d0 = ((int*)(dsm + S_DIDX))[r0];
        int d1 = ((int*)(dsm + S_DIDX))[r0 + 8];
#pragma unroll
        for (int nt = 0; nt < 2; nt++) {
            int jc = nt * 8 + (l & 3) * 2;
            float v0 = c2[mt][nt][0] + b2p[nt].x;
            float v1 = c2[mt][nt][1] + b2p[nt].y;
            *(float2*)&e_out[(base + r0) * 16 + jc] = make_float2(v0, v1);
            atomicAdd(g_agg + d0 * 16 + jc,     v0);
            atomicAdd(g_agg + d0 * 16 + jc + 1, v1);
            v0 = c2[mt][nt][2] + b2p[nt].x;
            v1 = c2[mt][nt][3] + b2p[nt].y;
            *(float2*)&e_out[(base + r0 + 8) * 16 + jc] = make_float2(v0, v1);
            atomicAdd(g_agg + d1 * 16 + jc,     v0);
            atomicAdd(g_agg + d1 * 16 + jc + 1, v1);
        }
    }
}

// ---------------------------------------------------------------------------
// node MLP  x_new = fO(concat(x, agg)). One node per thread (R15 version —
// the split-j variant regressed: duplicated input loads + shfl overhead).
// ---------------------------------------------------------------------------
__global__ void __launch_bounds__(128) node_kernel(
    const float* __restrict__ x,
    const float* __restrict__ W1, const float* __restrict__ b1,
    const float* __restrict__ W2, const float* __restrict__ b2,
    float* __restrict__ x_out)
{
    __shared__ float sW1[32 * 64];
    __shared__ float sW2[64 * 16];
    __shared__ float sb1[64];
    __shared__ float sb2[16];
    int tid = threadIdx.x;
#pragma unroll
    for (int r = 0; r < 16; r++) sW1[r * 128 + tid] = W1[r * 128 + tid];
#pragma unroll
    for (int r = 0; r < 8; r++) sW2[r * 128 + tid] = W2[r * 128 + tid];
    if (tid < 64) sb1[tid] = b1[tid];
    if (tid < 16) sb2[tid] = b2[tid];
    __syncthreads();

    int n = blockIdx.x * 128 + tid;
    if (n >= NN) return;

    float in[32];
#pragma unroll
    for (int q = 0; q < 4; q++) {
        float4 v = ((const float4*)x)[n * 4 + q];
        in[q*4+0]=v.x; in[q*4+1]=v.y; in[q*4+2]=v.z; in[q*4+3]=v.w;
        float4 a = ((const float4*)g_agg)[n * 4 + q];
        in[16+q*4+0]=a.x; in[16+q*4+1]=a.y; in[16+q*4+2]=a.z; in[16+q*4+3]=a.w;
    }
    float o[16];
#pragma unroll
    for (int c = 0; c < 16; c++) o[c] = sb2[c];
    for (int j = 0; j < 64; j++) {
        float h = sb1[j];
#pragma unroll
        for (int k = 0; k < 32; k++) h = fmaf(in[k], sW1[k * 64 + j], h);
        h = fmaxf(h, 0.f);
#pragma unroll
        for (int c = 0; c < 16; c++) o[c] = fmaf(h, sW2[j * 16 + c], o[c]);
    }
#pragma unroll
    for (int q = 0; q < 4; q++)
        ((float4*)x_out)[n * 4 + q] =
            make_float4(o[q*4+0], o[q*4+1], o[q*4+2], o[q*4+3]);
}

// ---------------------------------------------------------------------------
extern "C" void kernel_launch(void* const* d_in, const int* in_sizes, int n_in,
                              void* d_out, int out_size)
{
    const float* x     = (const float*)d_in[0];
    const int*   ei    = (const int*)d_in[1];    // edge_index: int32 (JAX x64 disabled)
    const float* e     = (const float*)d_in[2];
    const float* fRW1  = (const float*)d_in[3];
    const float* fRb1  = (const float*)d_in[4];
    const float* fRW2  = (const float*)d_in[5];
    const float* fRb2  = (const float*)d_in[6];
    const float* fOW1  = (const float*)d_in[7];
    const float* fOb1  = (const float*)d_in[8];
    const float* fOW2  = (const float*)d_in[9];
    const float* fOb2  = (const float*)d_in[10];

    float* x_new = (float*)d_out;            // [NN, 16]
    float* e_new = x_new + NN * 16;          // [NE, 16]

    cudaFuncSetAttribute(edge_kernel, cudaFuncAttributeMaxDynamicSharedMemorySize,
                         SMEM_TOTAL);

    prep_kernel<<<13, 256>>>(fRW1, fRW2);
    zero_agg_kernel<<<(NN * 16 / 4 + 255) / 256, 256>>>();
    edge_kernel<<<NE / 256, 256, SMEM_TOTAL>>>(x, ei, e, fRb1, fRb2, e_new);
    node_kernel<<<(NN + 127) / 128, 128>>>(x, fOW1, fOb1, fOW2, fOb2, x_new);
}